// round 7
// baseline (speedup 1.0000x reference)
#include <cuda_runtime.h>
#include <cuda_bf16.h>
#include <cstdint>

#define MDIM 4096
#define KDIM 4096
#define NDIM 4096
#define BB   32
#define NBCOLS 128
#define KBROWS 128
#define BM   256
#define THREADS 256
#define MAXBLK (KBROWS * NBCOLS)
#define BUFSTRIDE 32768                  // per-stage smem (hi 16K + lo 16K)
#define SMEM_BYTES (2 * BUFSTRIDE)       // 64 KB dynamic

// ---------------- device scratch ----------------
__device__ int g_cnt[NBCOLS];
__device__ int g_listn[NBCOLS * KBROWS];
__device__ int g_listi[NBCOLS * KBROWS];
// w in HMMA fragment order: per block, 512 u32 hi + 512 u32 lo
__device__ uint32_t g_wfrag[(size_t)MAXBLK * 1024];
// pre-tiled bf16 hi/lo x: [kblock][M][32]
__device__ __nv_bfloat16 g_xh[(size_t)KBROWS * MDIM * BB];
__device__ __nv_bfloat16 g_xl[(size_t)KBROWS * MDIM * BB];

__device__ __forceinline__ uint32_t smem_u32(const void* p) {
    uint32_t a;
    asm("{ .reg .u64 t; cvta.to.shared.u64 t, %1; cvt.u32.u64 %0, t; }" : "=r"(a) : "l"(p));
    return a;
}

// ---------------- parallel bucket: one warp per output column ----------------
__global__ void bucket_kernel(const int* __restrict__ idx_i,
                              const int* __restrict__ idx_j, int nnz) {
    const int j    = blockIdx.x * (blockDim.x >> 5) + (threadIdx.x >> 5);
    const int lane = threadIdx.x & 31;
    if (j >= NBCOLS) return;
    int cnt = 0;
    for (int base = 0; base < nnz; base += 32) {
        int n = base + lane;
        bool hit = (n < nnz) && (idx_j[n] == j);
        unsigned m = __ballot_sync(0xFFFFFFFFu, hit);
        if (hit) {
            int pos = cnt + __popc(m & ((1u << lane) - 1u));
            g_listn[j * KBROWS + pos] = n;
            g_listi[j * KBROWS + pos] = idx_i[n];
        }
        cnt += __popc(m);
    }
    if (lane == 0) g_cnt[j] = cnt;
}

// ---------------- x pre-convert: fp32 -> bf16 hi/lo, tiled [i][m][32] ----------------
__global__ __launch_bounds__(THREADS) void xconv_kernel(const float* __restrict__ x) {
    size_t o4 = (size_t)blockIdx.x * THREADS + threadIdx.x;   // float4-granular
    int kq = (int)(o4 & 7);
    int m  = (int)((o4 >> 3) & 4095);
    int i  = (int)(o4 >> 15);
    float4 v = reinterpret_cast<const float4*>(x)[(size_t)m * (KDIM / 4) + i * 8 + kq];
    __nv_bfloat162 h01 = __float22bfloat162_rn(make_float2(v.x, v.y));
    __nv_bfloat162 h23 = __float22bfloat162_rn(make_float2(v.z, v.w));
    float2 r01 = make_float2(v.x - __bfloat162float(__low2bfloat16(h01)),
                             v.y - __bfloat162float(__high2bfloat16(h01)));
    float2 r23 = make_float2(v.z - __bfloat162float(__low2bfloat16(h23)),
                             v.w - __bfloat162float(__high2bfloat16(h23)));
    __nv_bfloat162 l01 = __float22bfloat162_rn(r01);
    __nv_bfloat162 l23 = __float22bfloat162_rn(r23);
    uint2 hv, lv;
    hv.x = *reinterpret_cast<uint32_t*>(&h01);
    hv.y = *reinterpret_cast<uint32_t*>(&h23);
    lv.x = *reinterpret_cast<uint32_t*>(&l01);
    lv.y = *reinterpret_cast<uint32_t*>(&l23);
    reinterpret_cast<uint2*>(g_xh)[o4] = hv;
    reinterpret_cast<uint2*>(g_xl)[o4] = lv;
}

// ---------------- w -> HMMA fragment order, bf16 hi/lo ----------------
__global__ void wconv_kernel(const float* __restrict__ w) {
    __shared__ float ws[BB * BB];     // w[n] as [k][c]
    const int n = blockIdx.x;
    const int tid = threadIdx.x;
    const float* wn = w + (size_t)n * (BB * BB);
    #pragma unroll
    for (int q = 0; q < 4; ++q) ws[tid + q * THREADS] = wn[tid + q * THREADS];
    __syncthreads();
    #pragma unroll
    for (int q = 0; q < 4; ++q) {
        int oi   = tid + q * THREADS;        // 0..1023
        int hilo = oi >> 9;
        int rem  = oi & 511;
        int lane = rem & 31;
        int nt   = (rem >> 5) & 3;
        int reg  = (rem >> 7) & 1;
        int kc   = rem >> 8;
        int gid  = lane >> 2, tig = lane & 3;
        int c  = nt * 8 + gid;
        int k0 = kc * 16 + 2 * tig + reg * 8;
        float f0 = ws[k0 * BB + c];
        float f1 = ws[(k0 + 1) * BB + c];
        __nv_bfloat16 h0 = __float2bfloat16_rn(f0);
        __nv_bfloat16 h1 = __float2bfloat16_rn(f1);
        __nv_bfloat162 out;
        if (hilo == 0) {
            out = __nv_bfloat162(h0, h1);
        } else {
            out = __float22bfloat162_rn(make_float2(f0 - __bfloat162float(h0),
                                                    f1 - __bfloat162float(h1)));
        }
        g_wfrag[(size_t)n * 1024 + oi] = *reinterpret_cast<uint32_t*>(&out);
    }
}

// ---------------- main HMMA kernel: 2-stage cp.async pipeline ----------------
// x smem: 64B rows, 16B chunks XOR-swizzled: chunk' = (chunk + (row>>1)) & 3
__global__ __launch_bounds__(THREADS) void bsmm_mma_kernel(float* __restrict__ y)
{
    extern __shared__ __align__(16) char dsm[];

    const int j    = blockIdx.x;
    const int m0   = blockIdx.y * BM;
    const int tid  = threadIdx.x;
    const int wid  = tid >> 5;
    const int lane = tid & 31;
    const int gid  = lane >> 2;
    const int tig  = lane & 3;

    const int lrow = lane & 7;
    const int lm   = lane >> 3;
    const uint32_t sbase = smem_u32(dsm);

    const int R0 = wid * 32 + (lm & 1) * 8 + lrow;
    const int chunk_half = lm >> 1;

    float acc[2][4][4];
    #pragma unroll
    for (int s = 0; s < 2; ++s)
        #pragma unroll
        for (int t = 0; t < 4; ++t)
            #pragma unroll
            for (int r = 0; r < 4; ++r) acc[s][t][r] = 0.0f;

    const int cnt = g_cnt[j];
    const int* lstn = &g_listn[j * KBROWS];
    const int* lsti = &g_listi[j * KBROWS];

    // staging indices: thread handles 4 float4 per array (hi & lo)
    int st_r[4], st_off[4];
    #pragma unroll
    for (int t = 0; t < 4; ++t) {
        int idx = tid + t * THREADS;         // 0..1023
        int r = idx >> 2, c = idx & 3;
        st_r[t]   = idx * 16;
        st_off[t] = r * 64 + (((c + (r >> 1)) & 3) << 4);
    }

    // prefetch tile 0 into buffer 0
    if (cnt > 0) {
        const int i0 = lsti[0];
        const char* Hg = reinterpret_cast<const char*>(g_xh + ((size_t)i0 * MDIM + m0) * BB);
        const char* Lg = reinterpret_cast<const char*>(g_xl + ((size_t)i0 * MDIM + m0) * BB);
        #pragma unroll
        for (int t = 0; t < 4; ++t) {
            asm volatile("cp.async.cg.shared.global [%0], [%1], 16;"
                         :: "r"(sbase + st_off[t]), "l"(Hg + st_r[t]));
            asm volatile("cp.async.cg.shared.global [%0], [%1], 16;"
                         :: "r"(sbase + 16384 + st_off[t]), "l"(Lg + st_r[t]));
        }
        asm volatile("cp.async.commit_group;");
    }

    for (int e = 0; e < cnt; ++e) {
        const int n = lstn[e];
        const uint32_t buf = sbase + (uint32_t)(e & 1) * BUFSTRIDE;

        // ---- issue prefetch for tile e+1 into the other buffer ----
        const bool more = (e + 1 < cnt);
        if (more) {
            const int i1 = lsti[e + 1];
            const uint32_t nbuf = sbase + (uint32_t)((e + 1) & 1) * BUFSTRIDE;
            const char* Hg = reinterpret_cast<const char*>(g_xh + ((size_t)i1 * MDIM + m0) * BB);
            const char* Lg = reinterpret_cast<const char*>(g_xl + ((size_t)i1 * MDIM + m0) * BB);
            #pragma unroll
            for (int t = 0; t < 4; ++t) {
                asm volatile("cp.async.cg.shared.global [%0], [%1], 16;"
                             :: "r"(nbuf + st_off[t]), "l"(Hg + st_r[t]));
                asm volatile("cp.async.cg.shared.global [%0], [%1], 16;"
                             :: "r"(nbuf + 16384 + st_off[t]), "l"(Lg + st_r[t]));
            }
            asm volatile("cp.async.commit_group;");
            asm volatile("cp.async.wait_group 1;");   // tile e ready, e+1 in flight
        } else {
            asm volatile("cp.async.wait_group 0;");
        }
        __syncthreads();

        const uint32_t* wf = g_wfrag + ((size_t)n << 10);
        const uint32_t xh_base = buf;
        const uint32_t xl_base = buf + 16384;

        #pragma unroll
        for (int kc = 0; kc < 2; ++kc) {
            uint32_t ah[2][4], al[2][4];
            #pragma unroll
            for (int s = 0; s < 2; ++s) {
                int R = R0 + s * 16;
                int chunk = kc * 2 + chunk_half;
                uint32_t off = R * 64 + (((chunk + (R >> 1)) & 3) << 4);
                asm volatile("ldmatrix.sync.aligned.m8n8.x4.shared.b16 {%0,%1,%2,%3}, [%4];"
                             : "=r"(ah[s][0]), "=r"(ah[s][1]), "=r"(ah[s][2]), "=r"(ah[s][3])
                             : "r"(xh_base + off));
                asm volatile("ldmatrix.sync.aligned.m8n8.x4.shared.b16 {%0,%1,%2,%3}, [%4];"
                             : "=r"(al[s][0]), "=r"(al[s][1]), "=r"(al[s][2]), "=r"(al[s][3])
                             : "r"(xl_base + off));
            }
            #pragma unroll
            for (int nt = 0; nt < 4; ++nt) {
                uint32_t bh0 = wf[((kc * 2 + 0) * 4 + nt) * 32 + lane];
                uint32_t bh1 = wf[((kc * 2 + 1) * 4 + nt) * 32 + lane];
                uint32_t bl0 = wf[512 + ((kc * 2 + 0) * 4 + nt) * 32 + lane];
                uint32_t bl1 = wf[512 + ((kc * 2 + 1) * 4 + nt) * 32 + lane];
                #pragma unroll
                for (int s = 0; s < 2; ++s) {
                    float* d = acc[s][nt];
                    asm volatile(
                        "mma.sync.aligned.m16n8k16.row.col.f32.bf16.bf16.f32 "
                        "{%0,%1,%2,%3}, {%4,%5,%6,%7}, {%8,%9}, {%0,%1,%2,%3};"
                        : "+f"(d[0]), "+f"(d[1]), "+f"(d[2]), "+f"(d[3])
                        : "r"(ah[s][0]), "r"(ah[s][1]), "r"(ah[s][2]), "r"(ah[s][3]),
                          "r"(bh0), "r"(bh1));
                    asm volatile(
                        "mma.sync.aligned.m16n8k16.row.col.f32.bf16.bf16.f32 "
                        "{%0,%1,%2,%3}, {%4,%5,%6,%7}, {%8,%9}, {%0,%1,%2,%3};"
                        : "+f"(d[0]), "+f"(d[1]), "+f"(d[2]), "+f"(d[3])
                        : "r"(al[s][0]), "r"(al[s][1]), "r"(al[s][2]), "r"(al[s][3]),
                          "r"(bh0), "r"(bh1));
                    asm volatile(
                        "mma.sync.aligned.m16n8k16.row.col.f32.bf16.bf16.f32 "
                        "{%0,%1,%2,%3}, {%4,%5,%6,%7}, {%8,%9}, {%0,%1,%2,%3};"
                        : "+f"(d[0]), "+f"(d[1]), "+f"(d[2]), "+f"(d[3])
                        : "r"(ah[s][0]), "r"(ah[s][1]), "r"(ah[s][2]), "r"(ah[s][3]),
                          "r"(bl0), "r"(bl1));
                }
            }
        }
        __syncthreads();   // all warps done reading buf[e&1] before iter e+1 overwrites it
    }

    // ---- epilogue ----
    #pragma unroll
    for (int s = 0; s < 2; ++s) {
        #pragma unroll
        for (int nt = 0; nt < 4; ++nt) {
            const float* d = acc[s][nt];
            int row0 = m0 + wid * 32 + s * 16 + gid;
            int col  = j * BB + nt * 8 + tig * 2;
            *reinterpret_cast<float2*>(&y[(size_t)row0 * NDIM + col]) =
                make_float2(d[0], d[1]);
            *reinterpret_cast<float2*>(&y[(size_t)(row0 + 8) * NDIM + col]) =
                make_float2(d[2], d[3]);
        }
    }
}

extern "C" void kernel_launch(void* const* d_in, const int* in_sizes, int n_in,
                              void* d_out, int out_size)
{
    const float* x     = (const float*)d_in[0];
    const float* w     = (const float*)d_in[1];
    const int*   idx_i = (const int*)d_in[2];
    const int*   idx_j = (const int*)d_in[3];
    float*       y     = (float*)d_out;
    const int    nnz   = in_sizes[2];

    cudaFuncSetAttribute(bsmm_mma_kernel,
                         cudaFuncAttributeMaxDynamicSharedMemorySize, SMEM_BYTES);

    bucket_kernel<<<16, 256>>>(idx_i, idx_j, nnz);
    xconv_kernel<<<16384, THREADS>>>(x);
    wconv_kernel<<<nnz, THREADS>>>(w);

    dim3 grid(NBCOLS, MDIM / BM);
    bsmm_mma_kernel<<<grid, THREADS, SMEM_BYTES>>>(y);
}

// round 9
// speedup vs baseline: 1.2355x; 1.2355x over previous
#include <cuda_runtime.h>
#include <cuda_bf16.h>
#include <cstdint>

#define MDIM 4096
#define KDIM 4096
#define NDIM 4096
#define BB   32
#define NBCOLS 128
#define KBROWS 128
#define BM   256
#define THREADS 256
#define MAXBLK (KBROWS * NBCOLS)

// ---------------- device scratch ----------------
__device__ int g_cnt[NBCOLS];
__device__ int g_listn[NBCOLS * KBROWS];
__device__ int g_listi[NBCOLS * KBROWS];
// w fragments, LDG.128-ready: [n][hilo][nt][lane] -> uint4 = (kc0:reg0,reg1, kc1:reg0,reg1)
__device__ uint4 g_wf[(size_t)MAXBLK * 256];
// x A-fragments, LDG.128-ready: [i][t16][kc][lane] -> uint4 = (a0,a1,a2,a3), hi and lo arrays
__device__ uint4 g_xfh[(size_t)KBROWS * 256 * 2 * 32];
__device__ uint4 g_xfl[(size_t)KBROWS * 256 * 2 * 32];

// ---------------- parallel bucket: one warp per output column ----------------
__global__ void bucket_kernel(const int* __restrict__ idx_i,
                              const int* __restrict__ idx_j, int nnz) {
    const int j    = blockIdx.x * (blockDim.x >> 5) + (threadIdx.x >> 5);
    const int lane = threadIdx.x & 31;
    if (j >= NBCOLS) return;
    int cnt = 0;
    for (int base = 0; base < nnz; base += 32) {
        int n = base + lane;
        bool hit = (n < nnz) && (idx_j[n] == j);
        unsigned m = __ballot_sync(0xFFFFFFFFu, hit);
        if (hit) {
            int pos = cnt + __popc(m & ((1u << lane) - 1u));
            g_listn[j * KBROWS + pos] = n;
            g_listi[j * KBROWS + pos] = idx_i[n];
        }
        cnt += __popc(m);
    }
    if (lane == 0) g_cnt[j] = cnt;
}

// ---------------- x -> A-fragment order, bf16 hi/lo ----------------
// block = (i, 128-row chunk). Stage fp32 tile in smem, emit fragment uint4s.
__global__ __launch_bounds__(THREADS) void xconv_kernel(const float* __restrict__ x) {
    __shared__ float xs[128 * 32];
    const int i  = blockIdx.x >> 5;
    const int mc = blockIdx.x & 31;
    const int tid = threadIdx.x;

    const float4* X4 = reinterpret_cast<const float4*>(x);
    float4* XS4 = reinterpret_cast<float4*>(xs);
    #pragma unroll
    for (int t = 0; t < 4; ++t) {
        int idx = tid + t * THREADS;          // 0..1023
        int r = idx >> 3, c4 = idx & 7;
        XS4[r * 8 + c4] = X4[(size_t)(mc * 128 + r) * (KDIM / 4) + i * 8 + c4];
    }
    __syncthreads();

    #pragma unroll
    for (int it0 = 0; it0 < 2; ++it0) {
        int it   = tid + it0 * THREADS;       // 0..511
        int lane = it & 31;
        int kc   = (it >> 5) & 1;
        int t16  = it >> 6;                   // 0..7
        int gid  = lane >> 2, tig = lane & 3;
        int r0 = t16 * 16 + gid, r1 = r0 + 8;
        int c0 = kc * 16 + 2 * tig;
        int c2 = c0 + 8;

        float f[8];
        f[0] = xs[r0 * 32 + c0];     f[1] = xs[r0 * 32 + c0 + 1];
        f[2] = xs[r1 * 32 + c0];     f[3] = xs[r1 * 32 + c0 + 1];
        f[4] = xs[r0 * 32 + c2];     f[5] = xs[r0 * 32 + c2 + 1];
        f[6] = xs[r1 * 32 + c2];     f[7] = xs[r1 * 32 + c2 + 1];

        uint4 hv, lv;
        uint32_t* hw = reinterpret_cast<uint32_t*>(&hv);
        uint32_t* lw = reinterpret_cast<uint32_t*>(&lv);
        #pragma unroll
        for (int p = 0; p < 4; ++p) {
            __nv_bfloat16 h0 = __float2bfloat16_rn(f[2 * p]);
            __nv_bfloat16 h1 = __float2bfloat16_rn(f[2 * p + 1]);
            __nv_bfloat162 hp(h0, h1);
            __nv_bfloat162 lp = __float22bfloat162_rn(make_float2(
                f[2 * p]     - __bfloat162float(h0),
                f[2 * p + 1] - __bfloat162float(h1)));
            hw[p] = *reinterpret_cast<uint32_t*>(&hp);
            lw[p] = *reinterpret_cast<uint32_t*>(&lp);
        }
        size_t out = ((size_t)(i * 256 + mc * 8 + t16) * 2 + kc) * 32 + lane;
        g_xfh[out] = hv;
        g_xfl[out] = lv;
    }
}

// ---------------- w -> fragment order (uint4 per lane: kc0r0,kc0r1,kc1r0,kc1r1) ----------------
__global__ void wconv_kernel(const float* __restrict__ w) {
    __shared__ float ws[BB * BB];     // w[n] as [k][c]
    const int n = blockIdx.x;
    const int tid = threadIdx.x;
    const float* wn = w + (size_t)n * (BB * BB);
    #pragma unroll
    for (int q = 0; q < 4; ++q) ws[tid + q * THREADS] = wn[tid + q * THREADS];
    __syncthreads();
    uint32_t* WF = reinterpret_cast<uint32_t*>(g_wf);
    #pragma unroll
    for (int q = 0; q < 4; ++q) {
        int oi   = tid + q * THREADS;        // 0..1023
        int hilo = oi >> 9;
        int rem  = oi & 511;
        int nt   = rem >> 7;
        int lane = (rem >> 2) & 31;
        int word = rem & 3;
        int kc   = word >> 1, reg = word & 1;
        int gid  = lane >> 2, tig = lane & 3;
        int c  = nt * 8 + gid;
        int k0 = kc * 16 + 2 * tig + reg * 8;
        float f0 = ws[k0 * BB + c];
        float f1 = ws[(k0 + 1) * BB + c];
        __nv_bfloat16 h0 = __float2bfloat16_rn(f0);
        __nv_bfloat16 h1 = __float2bfloat16_rn(f1);
        __nv_bfloat162 out;
        if (hilo == 0) {
            out = __nv_bfloat162(h0, h1);
        } else {
            out = __float22bfloat162_rn(make_float2(f0 - __bfloat162float(h0),
                                                    f1 - __bfloat162float(h1)));
        }
        WF[(size_t)n * 1024 + oi] = *reinterpret_cast<uint32_t*>(&out);
    }
}

// ---------------- main HMMA kernel: direct fragment LDG, no smem, no barriers ----------------
__global__ __launch_bounds__(THREADS) void bsmm_mma_kernel(float* __restrict__ y)
{
    const int j    = blockIdx.x;
    const int m0   = blockIdx.y * BM;
    const int tid  = threadIdx.x;
    const int wid  = tid >> 5;
    const int lane = tid & 31;
    const int gid  = lane >> 2;
    const int tig  = lane & 3;

    const int t16base = (m0 >> 4) + wid * 2;   // stripe s adds +s

    float acc[2][4][4];
    #pragma unroll
    for (int s = 0; s < 2; ++s)
        #pragma unroll
        for (int t = 0; t < 4; ++t)
            #pragma unroll
            for (int r = 0; r < 4; ++r) acc[s][t][r] = 0.0f;

    const int cnt = g_cnt[j];
    const int* lstn = &g_listn[j * KBROWS];
    const int* lsti = &g_listi[j * KBROWS];

    for (int e = 0; e < cnt; ++e) {
        const int n = lstn[e];
        const int i = lsti[e];

        // ---- A fragments: 8 coalesced LDG.128 ----
        uint4 xh[2][2], xl[2][2];
        #pragma unroll
        for (int s = 0; s < 2; ++s)
            #pragma unroll
            for (int kc = 0; kc < 2; ++kc) {
                size_t idx = ((size_t)(i * 256 + t16base + s) * 2 + kc) * 32 + lane;
                xh[s][kc] = __ldg(&g_xfh[idx]);
                xl[s][kc] = __ldg(&g_xfl[idx]);
            }
        // ---- B fragments: 8 coalesced LDG.128 ----
        uint4 wh[4], wl[4];
        const uint4* wf = g_wf + (size_t)n * 256 + lane;
        #pragma unroll
        for (int nt = 0; nt < 4; ++nt) {
            wh[nt] = __ldg(&wf[nt * 32]);
            wl[nt] = __ldg(&wf[128 + nt * 32]);
        }

        #pragma unroll
        for (int kc = 0; kc < 2; ++kc) {
            #pragma unroll
            for (int nt = 0; nt < 4; ++nt) {
                uint32_t bh0 = kc ? wh[nt].z : wh[nt].x;
                uint32_t bh1 = kc ? wh[nt].w : wh[nt].y;
                uint32_t bl0 = kc ? wl[nt].z : wl[nt].x;
                uint32_t bl1 = kc ? wl[nt].w : wl[nt].y;
                #pragma unroll
                for (int s = 0; s < 2; ++s) {
                    const uint4& A  = xh[s][kc];
                    const uint4& Al = xl[s][kc];
                    float* d = acc[s][nt];
                    asm volatile(
                        "mma.sync.aligned.m16n8k16.row.col.f32.bf16.bf16.f32 "
                        "{%0,%1,%2,%3}, {%4,%5,%6,%7}, {%8,%9}, {%0,%1,%2,%3};"
                        : "+f"(d[0]), "+f"(d[1]), "+f"(d[2]), "+f"(d[3])
                        : "r"(A.x), "r"(A.y), "r"(A.z), "r"(A.w), "r"(bh0), "r"(bh1));
                    asm volatile(
                        "mma.sync.aligned.m16n8k16.row.col.f32.bf16.bf16.f32 "
                        "{%0,%1,%2,%3}, {%4,%5,%6,%7}, {%8,%9}, {%0,%1,%2,%3};"
                        : "+f"(d[0]), "+f"(d[1]), "+f"(d[2]), "+f"(d[3])
                        : "r"(Al.x), "r"(Al.y), "r"(Al.z), "r"(Al.w), "r"(bh0), "r"(bh1));
                    asm volatile(
                        "mma.sync.aligned.m16n8k16.row.col.f32.bf16.bf16.f32 "
                        "{%0,%1,%2,%3}, {%4,%5,%6,%7}, {%8,%9}, {%0,%1,%2,%3};"
                        : "+f"(d[0]), "+f"(d[1]), "+f"(d[2]), "+f"(d[3])
                        : "r"(A.x), "r"(A.y), "r"(A.z), "r"(A.w), "r"(bl0), "r"(bl1));
                }
            }
        }
    }

    // ---- epilogue ----
    #pragma unroll
    for (int s = 0; s < 2; ++s) {
        #pragma unroll
        for (int nt = 0; nt < 4; ++nt) {
            const float* d = acc[s][nt];
            int row0 = m0 + wid * 32 + s * 16 + gid;
            int col  = j * BB + nt * 8 + tig * 2;
            *reinterpret_cast<float2*>(&y[(size_t)row0 * NDIM + col]) =
                make_float2(d[0], d[1]);
            *reinterpret_cast<float2*>(&y[(size_t)(row0 + 8) * NDIM + col]) =
                make_float2(d[2], d[3]);
        }
    }
}

extern "C" void kernel_launch(void* const* d_in, const int* in_sizes, int n_in,
                              void* d_out, int out_size)
{
    const float* x     = (const float*)d_in[0];
    const float* w     = (const float*)d_in[1];
    const int*   idx_i = (const int*)d_in[2];
    const int*   idx_j = (const int*)d_in[3];
    float*       y     = (float*)d_out;
    const int    nnz   = in_sizes[2];

    bucket_kernel<<<16, 256>>>(idx_i, idx_j, nnz);
    xconv_kernel<<<KBROWS * 32, THREADS>>>(x);
    wconv_kernel<<<nnz, THREADS>>>(w);

    dim3 grid(NBCOLS, MDIM / BM);
    bsmm_mma_kernel<<<grid, THREADS>>>(y);
}

// round 10
// speedup vs baseline: 1.3947x; 1.1288x over previous
#include <cuda_runtime.h>
#include <cuda_bf16.h>
#include <cstdint>

#define MDIM 4096
#define KDIM 4096
#define NDIM 4096
#define BB   32
#define NBCOLS 128
#define KBROWS 128
#define BM   256
#define THREADS 256
#define MAXBLK (KBROWS * NBCOLS)
#define XCONV_BLOCKS (KBROWS * 32)     // 4096

// ---------------- device scratch ----------------
__device__ int g_cnt[NBCOLS];
__device__ int g_listn[NBCOLS * KBROWS];
__device__ int g_listi[NBCOLS * KBROWS];
// w fragments: [n][hilo][nt][lane] -> uint4 = (kc0:reg0,reg1, kc1:reg0,reg1)
__device__ uint4 g_wf[(size_t)MAXBLK * 256];
// x A-fragments: [i][t16][kc][lane] -> uint4, hi and lo arrays
__device__ uint4 g_xfh[(size_t)KBROWS * 256 * 2 * 32];
__device__ uint4 g_xfl[(size_t)KBROWS * 256 * 2 * 32];

// ---------------- fused prep kernel ----------------
// blocks [0, XCONV_BLOCKS)                : x -> A-fragment conversion
// blocks [XCONV_BLOCKS, XCONV_BLOCKS+nnz) : w -> B-fragment conversion
// blocks [XCONV_BLOCKS+nnz, +16)          : bucketing (8 warps each, 1 col/warp)
__global__ __launch_bounds__(THREADS) void prep_kernel(
    const float* __restrict__ x,
    const float* __restrict__ w,
    const int*  __restrict__ idx_i,
    const int*  __restrict__ idx_j,
    int nnz)
{
    __shared__ float sbuf[128 * 32];
    const int bid = blockIdx.x;
    const int tid = threadIdx.x;

    if (bid < XCONV_BLOCKS) {
        // ---------- xconv ----------
        const int i  = bid >> 5;
        const int mc = bid & 31;
        const float4* X4 = reinterpret_cast<const float4*>(x);
        float4* XS4 = reinterpret_cast<float4*>(sbuf);
        #pragma unroll
        for (int t = 0; t < 4; ++t) {
            int idx = tid + t * THREADS;
            int r = idx >> 3, c4 = idx & 7;
            XS4[r * 8 + c4] = X4[(size_t)(mc * 128 + r) * (KDIM / 4) + i * 8 + c4];
        }
        __syncthreads();
        #pragma unroll
        for (int it0 = 0; it0 < 2; ++it0) {
            int it   = tid + it0 * THREADS;
            int lane = it & 31;
            int kc   = (it >> 5) & 1;
            int t16  = it >> 6;
            int gid  = lane >> 2, tig = lane & 3;
            int r0 = t16 * 16 + gid, r1 = r0 + 8;
            int c0 = kc * 16 + 2 * tig;
            int c2 = c0 + 8;
            float f[8];
            f[0] = sbuf[r0 * 32 + c0];  f[1] = sbuf[r0 * 32 + c0 + 1];
            f[2] = sbuf[r1 * 32 + c0];  f[3] = sbuf[r1 * 32 + c0 + 1];
            f[4] = sbuf[r0 * 32 + c2];  f[5] = sbuf[r0 * 32 + c2 + 1];
            f[6] = sbuf[r1 * 32 + c2];  f[7] = sbuf[r1 * 32 + c2 + 1];
            uint4 hv, lv;
            uint32_t* hw = reinterpret_cast<uint32_t*>(&hv);
            uint32_t* lw = reinterpret_cast<uint32_t*>(&lv);
            #pragma unroll
            for (int p = 0; p < 4; ++p) {
                __nv_bfloat16 h0 = __float2bfloat16_rn(f[2 * p]);
                __nv_bfloat16 h1 = __float2bfloat16_rn(f[2 * p + 1]);
                __nv_bfloat162 hp(h0, h1);
                __nv_bfloat162 lp = __float22bfloat162_rn(make_float2(
                    f[2 * p]     - __bfloat162float(h0),
                    f[2 * p + 1] - __bfloat162float(h1)));
                hw[p] = *reinterpret_cast<uint32_t*>(&hp);
                lw[p] = *reinterpret_cast<uint32_t*>(&lp);
            }
            size_t out = ((size_t)(i * 256 + mc * 8 + t16) * 2 + kc) * 32 + lane;
            g_xfh[out] = hv;
            g_xfl[out] = lv;
        }
    } else if (bid < XCONV_BLOCKS + nnz) {
        // ---------- wconv ----------
        const int n = bid - XCONV_BLOCKS;
        const float* wn = w + (size_t)n * (BB * BB);
        #pragma unroll
        for (int q = 0; q < 4; ++q) sbuf[tid + q * THREADS] = wn[tid + q * THREADS];
        __syncthreads();
        uint32_t* WF = reinterpret_cast<uint32_t*>(g_wf);
        #pragma unroll
        for (int q = 0; q < 4; ++q) {
            int oi   = tid + q * THREADS;
            int hilo = oi >> 9;
            int rem  = oi & 511;
            int nt   = rem >> 7;
            int lane = (rem >> 2) & 31;
            int word = rem & 3;
            int kc   = word >> 1, reg = word & 1;
            int gid  = lane >> 2, tig = lane & 3;
            int c  = nt * 8 + gid;
            int k0 = kc * 16 + 2 * tig + reg * 8;
            float f0 = sbuf[k0 * BB + c];
            float f1 = sbuf[(k0 + 1) * BB + c];
            __nv_bfloat16 h0 = __float2bfloat16_rn(f0);
            __nv_bfloat16 h1 = __float2bfloat16_rn(f1);
            __nv_bfloat162 out;
            if (hilo == 0) {
                out = __nv_bfloat162(h0, h1);
            } else {
                out = __float22bfloat162_rn(make_float2(f0 - __bfloat162float(h0),
                                                        f1 - __bfloat162float(h1)));
            }
            WF[(size_t)n * 1024 + oi] = *reinterpret_cast<uint32_t*>(&out);
        }
    } else {
        // ---------- bucket: one warp per output column ----------
        const int blk  = bid - XCONV_BLOCKS - nnz;    // 0..15
        const int j    = blk * 8 + (tid >> 5);
        const int lane = tid & 31;
        if (j < NBCOLS) {
            int cnt = 0;
            for (int base = 0; base < nnz; base += 32) {
                int n = base + lane;
                bool hit = (n < nnz) && (idx_j[n] == j);
                unsigned m = __ballot_sync(0xFFFFFFFFu, hit);
                if (hit) {
                    int pos = cnt + __popc(m & ((1u << lane) - 1u));
                    g_listn[j * KBROWS + pos] = n;
                    g_listi[j * KBROWS + pos] = idx_i[n];
                }
                cnt += __popc(m);
            }
            if (lane == 0) g_cnt[j] = cnt;
        }
    }
}

// ---------------- main HMMA kernel ----------------
__global__ __launch_bounds__(THREADS) void bsmm_mma_kernel(float* __restrict__ y)
{
    __shared__ int s_n[KBROWS];
    __shared__ int s_i[KBROWS];

    const int j    = blockIdx.x;
    const int m0   = blockIdx.y * BM;
    const int tid  = threadIdx.x;
    const int wid  = tid >> 5;
    const int lane = tid & 31;
    const int gid  = lane >> 2;
    const int tig  = lane & 3;

    const int t16base = (m0 >> 4) + wid * 2;

    const int cnt = g_cnt[j];
    if (tid < cnt) {
        s_n[tid] = g_listn[j * KBROWS + tid];
        s_i[tid] = g_listi[j * KBROWS + tid];
    }
    __syncthreads();

    float acc[2][4][4];
    #pragma unroll
    for (int s = 0; s < 2; ++s)
        #pragma unroll
        for (int t = 0; t < 4; ++t)
            #pragma unroll
            for (int r = 0; r < 4; ++r) acc[s][t][r] = 0.0f;

    for (int e = 0; e < cnt; ++e) {
        const int n = s_n[e];
        const int i = s_i[e];

        // ---- A fragments: 8 coalesced LDG.128 ----
        uint4 xh[2][2], xl[2][2];
        #pragma unroll
        for (int s = 0; s < 2; ++s)
            #pragma unroll
            for (int kc = 0; kc < 2; ++kc) {
                size_t idx = ((size_t)(i * 256 + t16base + s) * 2 + kc) * 32 + lane;
                xh[s][kc] = __ldg(&g_xfh[idx]);
                xl[s][kc] = __ldg(&g_xfl[idx]);
            }
        // ---- B fragments: 8 coalesced LDG.128 ----
        uint4 wh[4], wl[4];
        const uint4* wf = g_wf + (size_t)n * 256 + lane;
        #pragma unroll
        for (int nt = 0; nt < 4; ++nt) {
            wh[nt] = __ldg(&wf[nt * 32]);
            wl[nt] = __ldg(&wf[128 + nt * 32]);
        }

        // ---- MMAs interleaved by term: consecutive MMAs hit different accs ----
        #pragma unroll
        for (int kc = 0; kc < 2; ++kc) {
            #pragma unroll
            for (int term = 0; term < 3; ++term) {
                #pragma unroll
                for (int nt = 0; nt < 4; ++nt) {
                    uint32_t b0, b1;
                    if (term == 2) {            // xh * wl
                        b0 = kc ? wl[nt].z : wl[nt].x;
                        b1 = kc ? wl[nt].w : wl[nt].y;
                    } else {                    // xh*wh or xl*wh
                        b0 = kc ? wh[nt].z : wh[nt].x;
                        b1 = kc ? wh[nt].w : wh[nt].y;
                    }
                    #pragma unroll
                    for (int s = 0; s < 2; ++s) {
                        const uint4& A = (term == 1) ? xl[s][kc] : xh[s][kc];
                        float* d = acc[s][nt];
                        asm volatile(
                            "mma.sync.aligned.m16n8k16.row.col.f32.bf16.bf16.f32 "
                            "{%0,%1,%2,%3}, {%4,%5,%6,%7}, {%8,%9}, {%0,%1,%2,%3};"
                            : "+f"(d[0]), "+f"(d[1]), "+f"(d[2]), "+f"(d[3])
                            : "r"(A.x), "r"(A.y), "r"(A.z), "r"(A.w),
                              "r"(b0), "r"(b1));
                    }
                }
            }
        }
    }

    // ---- epilogue ----
    #pragma unroll
    for (int s = 0; s < 2; ++s) {
        #pragma unroll
        for (int nt = 0; nt < 4; ++nt) {
            const float* d = acc[s][nt];
            int row0 = m0 + wid * 32 + s * 16 + gid;
            int col  = j * BB + nt * 8 + tig * 2;
            *reinterpret_cast<float2*>(&y[(size_t)row0 * NDIM + col]) =
                make_float2(d[0], d[1]);
            *reinterpret_cast<float2*>(&y[(size_t)(row0 + 8) * NDIM + col]) =
                make_float2(d[2], d[3]);
        }
    }
}

extern "C" void kernel_launch(void* const* d_in, const int* in_sizes, int n_in,
                              void* d_out, int out_size)
{
    const float* x     = (const float*)d_in[0];
    const float* w     = (const float*)d_in[1];
    const int*   idx_i = (const int*)d_in[2];
    const int*   idx_j = (const int*)d_in[3];
    float*       y     = (float*)d_out;
    const int    nnz   = in_sizes[2];

    prep_kernel<<<XCONV_BLOCKS + nnz + 16, THREADS>>>(x, w, idx_i, idx_j, nnz);

    dim3 grid(NBCOLS, MDIM / BM);
    bsmm_mma_kernel<<<grid, THREADS>>>(y);
}

// round 11
// speedup vs baseline: 1.5915x; 1.1411x over previous
#include <cuda_runtime.h>
#include <cuda_fp16.h>
#include <cstdint>

#define MDIM 4096
#define KDIM 4096
#define NDIM 4096
#define BB   32
#define NBCOLS 128
#define KBROWS 128
#define BM   256
#define THREADS 256
#define MAXBLK (KBROWS * NBCOLS)
#define XCONV_BLOCKS (KBROWS * 32)     // 4096

// ---------------- device scratch ----------------
__device__ int g_cnt[NBCOLS];
__device__ int g_listn[NBCOLS * KBROWS];
__device__ int g_listi[NBCOLS * KBROWS];
// w fragments fp16 hi/lo: [n][hilo][nt][lane] -> uint4 = (kc0:r0,r1, kc1:r0,r1)
__device__ uint4 g_wf[(size_t)MAXBLK * 256];
// x A-fragments fp16 (hi only): [i][t16][kc][lane] -> uint4
__device__ uint4 g_xf[(size_t)KBROWS * 256 * 2 * 32];

// ---------------- fused prep kernel ----------------
__global__ __launch_bounds__(THREADS) void prep_kernel(
    const float* __restrict__ x,
    const float* __restrict__ w,
    const int*  __restrict__ idx_i,
    const int*  __restrict__ idx_j,
    int nnz)
{
    __shared__ float sbuf[128 * 32];
    const int bid = blockIdx.x;
    const int tid = threadIdx.x;

    if (bid < XCONV_BLOCKS) {
        // ---------- xconv: fp32 -> fp16 A fragments ----------
        const int i  = bid >> 5;
        const int mc = bid & 31;
        const float4* X4 = reinterpret_cast<const float4*>(x);
        float4* XS4 = reinterpret_cast<float4*>(sbuf);
        #pragma unroll
        for (int t = 0; t < 4; ++t) {
            int idx = tid + t * THREADS;
            int r = idx >> 3, c4 = idx & 7;
            XS4[r * 8 + c4] = X4[(size_t)(mc * 128 + r) * (KDIM / 4) + i * 8 + c4];
        }
        __syncthreads();
        #pragma unroll
        for (int it0 = 0; it0 < 2; ++it0) {
            int it   = tid + it0 * THREADS;
            int lane = it & 31;
            int kc   = (it >> 5) & 1;
            int t16  = it >> 6;
            int gid  = lane >> 2, tig = lane & 3;
            int r0 = t16 * 16 + gid, r1 = r0 + 8;
            int c0 = kc * 16 + 2 * tig;
            int c2 = c0 + 8;
            float f[8];
            f[0] = sbuf[r0 * 32 + c0];  f[1] = sbuf[r0 * 32 + c0 + 1];
            f[2] = sbuf[r1 * 32 + c0];  f[3] = sbuf[r1 * 32 + c0 + 1];
            f[4] = sbuf[r0 * 32 + c2];  f[5] = sbuf[r0 * 32 + c2 + 1];
            f[6] = sbuf[r1 * 32 + c2];  f[7] = sbuf[r1 * 32 + c2 + 1];
            uint4 hv;
            uint32_t* hw = reinterpret_cast<uint32_t*>(&hv);
            #pragma unroll
            for (int p = 0; p < 4; ++p) {
                __half2 hp = __float22half2_rn(make_float2(f[2 * p], f[2 * p + 1]));
                hw[p] = *reinterpret_cast<uint32_t*>(&hp);
            }
            g_xf[((size_t)(i * 256 + mc * 8 + t16) * 2 + kc) * 32 + lane] = hv;
        }
    } else if (bid < XCONV_BLOCKS + nnz) {
        // ---------- wconv: fp32 -> fp16 hi/lo B fragments ----------
        const int n = bid - XCONV_BLOCKS;
        const float* wn = w + (size_t)n * (BB * BB);
        #pragma unroll
        for (int q = 0; q < 4; ++q) sbuf[tid + q * THREADS] = wn[tid + q * THREADS];
        __syncthreads();
        uint32_t* WF = reinterpret_cast<uint32_t*>(g_wf);
        #pragma unroll
        for (int q = 0; q < 4; ++q) {
            int oi   = tid + q * THREADS;        // 0..1023
            int hilo = oi >> 9;
            int rem  = oi & 511;
            int nt   = rem >> 7;
            int lane = (rem >> 2) & 31;
            int word = rem & 3;
            int kc   = word >> 1, reg = word & 1;
            int gid  = lane >> 2, tig = lane & 3;
            int c  = nt * 8 + gid;
            int k0 = kc * 16 + 2 * tig + reg * 8;
            float f0 = sbuf[k0 * BB + c];
            float f1 = sbuf[(k0 + 1) * BB + c];
            __half h0 = __float2half_rn(f0);
            __half h1 = __float2half_rn(f1);
            __half2 out;
            if (hilo == 0) {
                out = __halves2half2(h0, h1);
            } else {
                out = __float22half2_rn(make_float2(f0 - __half2float(h0),
                                                    f1 - __half2float(h1)));
            }
            WF[(size_t)n * 1024 + oi] = *reinterpret_cast<uint32_t*>(&out);
        }
    } else {
        // ---------- bucket: one warp per output column ----------
        const int blk  = bid - XCONV_BLOCKS - nnz;
        const int j    = blk * 8 + (tid >> 5);
        const int lane = tid & 31;
        if (j < NBCOLS) {
            int cnt = 0;
            for (int base = 0; base < nnz; base += 32) {
                int n = base + lane;
                bool hit = (n < nnz) && (idx_j[n] == j);
                unsigned m = __ballot_sync(0xFFFFFFFFu, hit);
                if (hit) {
                    int pos = cnt + __popc(m & ((1u << lane) - 1u));
                    g_listn[j * KBROWS + pos] = n;
                    g_listi[j * KBROWS + pos] = idx_i[n];
                }
                cnt += __popc(m);
            }
            if (lane == 0) g_cnt[j] = cnt;
        }
    }
}

// ---------------- main HMMA kernel: fp16 2-term split ----------------
__global__ __launch_bounds__(THREADS) void bsmm_mma_kernel(float* __restrict__ y)
{
    __shared__ int s_n[KBROWS];
    __shared__ int s_i[KBROWS];

    const int j    = blockIdx.x;
    const int m0   = blockIdx.y * BM;
    const int tid  = threadIdx.x;
    const int wid  = tid >> 5;
    const int lane = tid & 31;
    const int gid  = lane >> 2;
    const int tig  = lane & 3;

    const int t16base = (m0 >> 4) + wid * 2;

    const int cnt = g_cnt[j];
    if (tid < cnt) {
        s_n[tid] = g_listn[j * KBROWS + tid];
        s_i[tid] = g_listi[j * KBROWS + tid];
    }
    __syncthreads();

    float acc[2][4][4];
    #pragma unroll
    for (int s = 0; s < 2; ++s)
        #pragma unroll
        for (int t = 0; t < 4; ++t)
            #pragma unroll
            for (int r = 0; r < 4; ++r) acc[s][t][r] = 0.0f;

    for (int e = 0; e < cnt; ++e) {
        const int n = s_n[e];
        const int i = s_i[e];

        // ---- A fragments: 4 coalesced LDG.128 ----
        uint4 xa[2][2];
        #pragma unroll
        for (int s = 0; s < 2; ++s)
            #pragma unroll
            for (int kc = 0; kc < 2; ++kc)
                xa[s][kc] = __ldg(&g_xf[((size_t)(i * 256 + t16base + s) * 2 + kc) * 32 + lane]);
        // ---- B fragments: 8 coalesced LDG.128 ----
        uint4 wh[4], wl[4];
        const uint4* wf = g_wf + (size_t)n * 256 + lane;
        #pragma unroll
        for (int nt = 0; nt < 4; ++nt) {
            wh[nt] = __ldg(&wf[nt * 32]);
            wl[nt] = __ldg(&wf[128 + nt * 32]);
        }

        // ---- 2-term MMAs interleaved: same-acc revisit distance = 8 ----
        #pragma unroll
        for (int kc = 0; kc < 2; ++kc) {
            #pragma unroll
            for (int term = 0; term < 2; ++term) {
                #pragma unroll
                for (int nt = 0; nt < 4; ++nt) {
                    uint32_t b0, b1;
                    if (term == 0) {
                        b0 = kc ? wh[nt].z : wh[nt].x;
                        b1 = kc ? wh[nt].w : wh[nt].y;
                    } else {
                        b0 = kc ? wl[nt].z : wl[nt].x;
                        b1 = kc ? wl[nt].w : wl[nt].y;
                    }
                    #pragma unroll
                    for (int s = 0; s < 2; ++s) {
                        const uint4& A = xa[s][kc];
                        float* d = acc[s][nt];
                        asm volatile(
                            "mma.sync.aligned.m16n8k16.row.col.f32.f16.f16.f32 "
                            "{%0,%1,%2,%3}, {%4,%5,%6,%7}, {%8,%9}, {%0,%1,%2,%3};"
                            : "+f"(d[0]), "+f"(d[1]), "+f"(d[2]), "+f"(d[3])
                            : "r"(A.x), "r"(A.y), "r"(A.z), "r"(A.w),
                              "r"(b0), "r"(b1));
                    }
                }
            }
        }
    }

    // ---- epilogue ----
    #pragma unroll
    for (int s = 0; s < 2; ++s) {
        #pragma unroll
        for (int nt = 0; nt < 4; ++nt) {
            const float* d = acc[s][nt];
            int row0 = m0 + wid * 32 + s * 16 + gid;
            int col  = j * BB + nt * 8 + tig * 2;
            *reinterpret_cast<float2*>(&y[(size_t)row0 * NDIM + col]) =
                make_float2(d[0], d[1]);
            *reinterpret_cast<float2*>(&y[(size_t)(row0 + 8) * NDIM + col]) =
                make_float2(d[2], d[3]);
        }
    }
}

extern "C" void kernel_launch(void* const* d_in, const int* in_sizes, int n_in,
                              void* d_out, int out_size)
{
    const float* x     = (const float*)d_in[0];
    const float* w     = (const float*)d_in[1];
    const int*   idx_i = (const int*)d_in[2];
    const int*   idx_j = (const int*)d_in[3];
    float*       y     = (float*)d_out;
    const int    nnz   = in_sizes[2];

    prep_kernel<<<XCONV_BLOCKS + nnz + 16, THREADS>>>(x, w, idx_i, idx_j, nnz);

    dim3 grid(NBCOLS, MDIM / BM);
    bsmm_mma_kernel<<<grid, THREADS>>>(y);
}